// round 2
// baseline (speedup 1.0000x reference)
#include <cuda_runtime.h>

// Problem constants: q,k,v,out all (B=4, S=4096, H=16, D=64) float32.
// Key insight: the Hilbert gather + inverse scatter cancel because the
// attention is per-position (scores are [B,S,h,h]). So the kernel is a
// per-(b,s) pair of 8x8 head-vs-head attentions over d=64.
#define NPOS   16384      // B*S
#define HEADS  16
#define DIM    64
#define ROW4   17         // float4 per padded smem row (68 floats) -> bank-conflict-free
#define SCALE  0.125f     // 64^-0.5

__global__ __launch_bounds__(128, 8)
void hilbert_headattn_kernel(const float4* __restrict__ q,
                             const float4* __restrict__ k,
                             const float4* __restrict__ v,
                             float4* __restrict__ out)
{
    __shared__ float sq[HEADS * ROW4 * 4];
    __shared__ float sk[HEADS * ROW4 * 4];
    __shared__ float sv[HEADS * ROW4 * 4];
    __shared__ float sattn[128];          // [g][i][j] = [2][8][8]

    const int t = threadIdx.x;                       // 0..127
    const int base = blockIdx.x * (HEADS * DIM / 4); // 256 float4 per tensor per pos

    // ---- load 3 x 4KB tiles, remapping row stride 16 -> 17 float4 (pad) ----
#pragma unroll
    for (int r = 0; r < 2; r++) {
        const int f   = t + r * 128;          // 0..255
        const int row = f >> 4;
        const int col = f & 15;
        const int sidx = row * ROW4 + col;
        reinterpret_cast<float4*>(sq)[sidx] = q[base + f];
        reinterpret_cast<float4*>(sk)[sidx] = k[base + f];
        reinterpret_cast<float4*>(sv)[sidx] = v[base + f];
    }
    __syncthreads();

    // ---- scores: thread t -> (g = t>>6, i = (t>>3)&7, j = t&7) ----
    {
        const int g  = t >> 6;
        const int i  = (t >> 3) & 7;
        const int j  = t & 7;
        const int hi = g * 8 + i;
        const int hj = g * 8 + j;
        const float* qrow = sq + hi * (ROW4 * 4);
        const float* krow = sk + hj * (ROW4 * 4);
        float acc = 0.f;
#pragma unroll
        for (int d = 0; d < DIM; d++) acc += qrow[d] * krow[d];
        acc *= SCALE;

        // softmax over j: j lives in aligned 8-lane groups -> xor shuffles 1,2,4
        float m = acc;
#pragma unroll
        for (int o = 1; o < 8; o <<= 1)
            m = fmaxf(m, __shfl_xor_sync(0xffffffffu, m, o));
        const float e = __expf(acc - m);
        float ssum = e;
#pragma unroll
        for (int o = 1; o < 8; o <<= 1)
            ssum += __shfl_xor_sync(0xffffffffu, ssum, o);
        sattn[t] = e / ssum;
    }
    __syncthreads();

    // ---- output: thread t -> head h = t>>3, dims [db, db+8) with db = (t&7)*8 ----
    {
        const int h  = t >> 3;          // 0..15
        const int db = (t & 7) * 8;     // 0,8,...,56
        const int go = h >> 3;          // group
        const float* ap = sattn + go * 64 + (h & 7) * 8;   // attn[i][0..7]

        float o0[8];
#pragma unroll
        for (int d = 0; d < 8; d++) o0[d] = 0.f;
#pragma unroll
        for (int jj = 0; jj < 8; jj++) {
            const float a = ap[jj];
            const float* vrow = sv + (go * 8 + jj) * (ROW4 * 4) + db;
#pragma unroll
            for (int d = 0; d < 8; d++) o0[d] += a * vrow[d];
        }
        float4* op = out + base + h * (DIM / 4) + (db >> 2);
        op[0] = make_float4(o0[0], o0[1], o0[2], o0[3]);
        op[1] = make_float4(o0[4], o0[5], o0[6], o0[7]);
    }
}

extern "C" void kernel_launch(void* const* d_in, const int* in_sizes, int n_in,
                              void* d_out, int out_size)
{
    const float4* q = (const float4*)d_in[0];
    const float4* k = (const float4*)d_in[1];
    const float4* v = (const float4*)d_in[2];
    float4* o       = (float4*)d_out;
    hilbert_headattn_kernel<<<NPOS, 128>>>(q, k, v, o);
}

// round 3
// speedup vs baseline: 1.1018x; 1.1018x over previous
#include <cuda_runtime.h>

// q,k,v,out: (B=4, S=4096, H=16, D=64) f32. Hilbert gather/scatter cancel
// (attention is per-position), leaving per-(b,s) 8x8 head-vs-head attention
// in two head groups of 8.
//
// R3 design: one warp per (position, group). No shared memory at all.
// Lane l owns head i = l>>2, dim chunk c = l&3 (16 floats) of q/k/v in
// registers. Scores + AV via register shuffles; softmax fully in-register.
#define NPOS  16384
#define SCALE 0.125f

__global__ __launch_bounds__(256)
void hilbert_headattn_kernel(const float4* __restrict__ q,
                             const float4* __restrict__ k,
                             const float4* __restrict__ v,
                             float4* __restrict__ out)
{
    const int lane = threadIdx.x & 31;
    const int wid  = (blockIdx.x * (blockDim.x >> 5)) + (threadIdx.x >> 5);
    // warp -> (position, group)
    const int pos  = wid >> 1;
    const int g    = wid & 1;
    const int c    = lane & 3;          // 16-float chunk within the 64-dim row

    // float4 base: pos*256 (1024 floats/pos) + g*128 (512 floats/group)
    const int base = pos * 256 + g * 128 + lane * 4;

    float qr[16], kr[16], vr[16];
#pragma unroll
    for (int m = 0; m < 4; m++) {
        float4 t;
        t = q[base + m]; qr[4*m] = t.x; qr[4*m+1] = t.y; qr[4*m+2] = t.z; qr[4*m+3] = t.w;
        t = k[base + m]; kr[4*m] = t.x; kr[4*m+1] = t.y; kr[4*m+2] = t.z; kr[4*m+3] = t.w;
        t = v[base + m]; vr[4*m] = t.x; vr[4*m+1] = t.y; vr[4*m+2] = t.z; vr[4*m+3] = t.w;
    }

    // ---- scores s[j] = (q[i] . k[j]) * SCALE, i = lane>>2 ----
    float s[8];
#pragma unroll
    for (int j = 0; j < 8; j++) {
        const int src = j * 4 + c;      // lane holding k[j, chunk c]
        float acc = 0.f;
#pragma unroll
        for (int m = 0; m < 16; m++)
            acc = fmaf(qr[m], __shfl_sync(0xffffffffu, kr[m], src), acc);
        // reduce partial over the 4 chunks of head i
        acc += __shfl_xor_sync(0xffffffffu, acc, 1);
        acc += __shfl_xor_sync(0xffffffffu, acc, 2);
        s[j] = acc * SCALE;
    }

    // ---- softmax over j, fully in-register (row replicated across 4 lanes) ----
    float mx = s[0];
#pragma unroll
    for (int j = 1; j < 8; j++) mx = fmaxf(mx, s[j]);
    float sum = 0.f;
#pragma unroll
    for (int j = 0; j < 8; j++) { s[j] = __expf(s[j] - mx); sum += s[j]; }
    const float inv = __frcp_rn(sum);
#pragma unroll
    for (int j = 0; j < 8; j++) s[j] *= inv;

    // ---- out[i, chunk c] = sum_j s[j] * v[j, chunk c] ----
    float o[16];
#pragma unroll
    for (int m = 0; m < 16; m++) o[m] = 0.f;
#pragma unroll
    for (int j = 0; j < 8; j++) {
        const int src = j * 4 + c;
        const float a = s[j];
#pragma unroll
        for (int m = 0; m < 16; m++)
            o[m] = fmaf(a, __shfl_sync(0xffffffffu, vr[m], src), o[m]);
    }

#pragma unroll
    for (int m = 0; m < 4; m++)
        out[base + m] = make_float4(o[4*m], o[4*m+1], o[4*m+2], o[4*m+3]);
}

extern "C" void kernel_launch(void* const* d_in, const int* in_sizes, int n_in,
                              void* d_out, int out_size)
{
    const float4* q = (const float4*)d_in[0];
    const float4* k = (const float4*)d_in[1];
    const float4* v = (const float4*)d_in[2];
    float4* o       = (float4*)d_out;
    // 256 threads = 8 warps = 4 positions per CTA; 2 warps per position
    hilbert_headattn_kernel<<<NPOS / 4, 256>>>(q, k, v, o);
}